// round 11
// baseline (speedup 1.0000x reference)
#include <cuda_runtime.h>
#include <cstdint>

#define EPS 0.0001f
#define N_DIFFS 4194304

// streaming int4 load with 256B L2 prefetch hint (sequential stream -> no waste)
__device__ __forceinline__ int4 ldg_cs_256(const int4* p) {
    int4 v;
    asm volatile("ld.global.cs.nc.L2::256B.v4.u32 {%0,%1,%2,%3}, [%4];"
                 : "=r"(v.x), "=r"(v.y), "=r"(v.z), "=r"(v.w) : "l"(p));
    return v;
}

__device__ __forceinline__ void stg_cs(float4* p, float4 v) {
    asm volatile("st.global.cs.v4.f32 [%0], {%1,%2,%3,%4};"
                 :: "l"(p), "f"(v.x), "f"(v.y), "f"(v.z), "f"(v.w) : "memory");
}

__global__ void __launch_bounds__(256, 8)
perf_model_kernel(const float* __restrict__ bin_centers,
                  const int*   __restrict__ obs_idx,
                  const float* __restrict__ lb1p,
                  const float* __restrict__ ub1p,
                  const float* __restrict__ lb2p,
                  const float* __restrict__ ub2p,
                  const float* __restrict__ respp,
                  float* __restrict__ out)
{
    int t = blockIdx.x * blockDim.x + threadIdx.x;   // one thread = 4 rows
    long long base_row = (long long)t * 4;

    // 4 rows * 3 ints = 12 ints = 3 x int4 (16B aligned); issue first,
    // each with a 256B L2 prefetch hint -> half the L2 request count
    const int4* p = reinterpret_cast<const int4*>(obs_idx + base_row * 3);
    int4 v0 = ldg_cs_256(p + 0);
    int4 v1 = ldg_cs_256(p + 1);
    int4 v2 = ldg_cs_256(p + 2);

    // uniform scalar prep (identical across threads; overlaps the LDG flight)
    float a1 = __ldg(lb1p), b1 = __ldg(ub1p);
    float a2 = __ldg(lb2p), b2 = __ldg(ub2p);
    float nlb1 = __frcp_rn(1.0f + __expf(-fminf(a1, b1)));
    float nub1 = __frcp_rn(1.0f + __expf(-fmaxf(a1, b1)));
    float nlb2 = __frcp_rn(1.0f + __expf(-fminf(a2, b2)));
    float nub2 = __frcp_rn(1.0f + __expf(-fmaxf(a2, b2)));
    float r    = __frcp_rn(1.0f + __expf(-__ldg(respp)));
    float inv1 = __frcp_rn(nub1 - nlb1 + EPS);
    float inv2 = __frcp_rn(nub2 - nlb2 + EPS);
    float c1 = nub1 * inv1;
    float c2 = nub2 * inv2;

    // dependent gathers from the L1-resident 4KB table
    float x0a = __ldg(bin_centers + v0.x), x0b = __ldg(bin_centers + v0.y);
    float x1a = __ldg(bin_centers + v0.w), x1b = __ldg(bin_centers + v1.x);
    float x2a = __ldg(bin_centers + v1.z), x2b = __ldg(bin_centers + v1.w);
    float x3a = __ldg(bin_centers + v2.y), x3b = __ldg(bin_centers + v2.z);

    // perf factor = saturate((ub - x) * inv) = saturate(fma(-x, inv, ub*inv))
    float4 o;
    o.x = __saturatef(fmaf(-x0a, inv1, c1)) * __saturatef(fmaf(-x0b, inv2, c2)) * r;
    o.y = __saturatef(fmaf(-x1a, inv1, c1)) * __saturatef(fmaf(-x1b, inv2, c2)) * r;
    o.z = __saturatef(fmaf(-x2a, inv1, c1)) * __saturatef(fmaf(-x2b, inv2, c2)) * r;
    o.w = __saturatef(fmaf(-x3a, inv1, c1)) * __saturatef(fmaf(-x3b, inv2, c2)) * r;

    // streaming store (evict-first)
    stg_cs(reinterpret_cast<float4*>(out) + t, o);
}

extern "C" void kernel_launch(void* const* d_in, const int* in_sizes, int n_in,
                              void* d_out, int out_size)
{
    // metadata order: bin_centers, obs_idx, lb1, ub1, lb2, ub2, resp
    const float* bin_centers = (const float*)d_in[0];
    const int*   obs_idx     = (const int*)  d_in[1];
    const float* lb1         = (const float*)d_in[2];
    const float* ub1         = (const float*)d_in[3];
    const float* lb2         = (const float*)d_in[4];
    const float* ub2         = (const float*)d_in[5];
    const float* resp        = (const float*)d_in[6];
    float* out = (float*)d_out;

    const int rows_per_thread = 4;
    const int threads = 256;
    int n_threads = N_DIFFS / rows_per_thread;           // 1,048,576
    int blocks = (n_threads + threads - 1) / threads;    // 4096

    perf_model_kernel<<<blocks, threads>>>(bin_centers, obs_idx,
                                           lb1, ub1, lb2, ub2, resp, out);
}